// round 9
// baseline (speedup 1.0000x reference)
#include <cuda_runtime.h>
#include <cuda_bf16.h>

#define NX 1024
#define NCELL 1023
#define EPSV 1e-10f
#define BLOCK_T 256
#define PTS_PER_THREAD 4   // one group of 4 points per thread (R7 winning shape)

// Scratch (__device__ globals — allocation-free rule)
__device__ float2 g_cellx[NCELL];           // (x_i, 1/max(dx,EPS)) per cell
__device__ float2 g_celly[NCELL];
__device__ float4 g_quad[(NX - 1) * NX];    // {u00,u10,u01,u11} per cell (ix<<10 | iy)

// ---------------------------------------------------------------------------
// Builder: blocks 0..1022 pack quad rows; blocks 1023/1024 build the x/y
// adaptive grids (shfl scan) and emit the per-cell (x_i, rdx) tables.
// ---------------------------------------------------------------------------
__device__ __forceinline__ void build_one_grid(const float* __restrict__ inc,
                                               float2* __restrict__ cells) {
    __shared__ float scum[1024];
    __shared__ float sg[1024];
    __shared__ float swarp[8];

    const int t    = threadIdx.x;       // 0..255
    const int lane = t & 31;
    const int warp = t >> 5;

    float v[4];
    #pragma unroll
    for (int j = 0; j < 4; j++) {
        int idx = 4 * t + j;
        float val = 0.0f;
        if (idx < 1023) {
            float xv = inc[idx];
            float sp = fmaxf(xv, 0.0f) + log1pf(expf(-fabsf(xv)));  // softplus
            val = fmaxf(sp, 1e-6f);
        }
        v[j] = val;
    }
    float c0 = v[0];
    float c1 = c0 + v[1];
    float c2 = c1 + v[2];
    float c3 = c2 + v[3];

    float incl = c3;
    #pragma unroll
    for (int off = 1; off < 32; off <<= 1) {
        float up = __shfl_up_sync(0xffffffff, incl, off);
        if (lane >= off) incl += up;
    }
    float thr_excl = incl - c3;
    if (lane == 31) swarp[warp] = incl;
    __syncthreads();

    if (warp == 0 && lane < 8) {
        float w = swarp[lane];
        #pragma unroll
        for (int off = 1; off < 8; off <<= 1) {
            float up = __shfl_up_sync(0xff, w, off);
            if (lane >= off) w += up;
        }
        swarp[lane] = w - swarp[lane];
    }
    __syncthreads();

    float pref = swarp[warp] + thr_excl;
    scum[4 * t + 0] = pref + c0;
    scum[4 * t + 1] = pref + c1;
    scum[4 * t + 2] = pref + c2;
    scum[4 * t + 3] = pref + c3;
    __syncthreads();

    float total = scum[1022];
    if (t == 0) sg[0] = 0.0f;
    #pragma unroll
    for (int j = 0; j < 4; j++) {
        int idx = 4 * t + j;
        if (idx < 1022)       sg[idx + 1] = scum[idx] / total;
        else if (idx == 1022) sg[1023]    = 1.0f;
    }
    __syncthreads();

    #pragma unroll
    for (int j = 0; j < 4; j++) {
        int idx = 4 * t + j;
        if (idx < NCELL) {
            float xi  = sg[idx];
            float rdx = 1.0f / fmaxf(sg[idx + 1] - xi, EPSV);
            cells[idx] = make_float2(xi, rdx);
        }
    }
}

__global__ __launch_bounds__(BLOCK_T)
void build_all(const float* __restrict__ incx,
               const float* __restrict__ incy,
               const float* __restrict__ u) {
    int bx = blockIdx.x;
    if (bx < NX - 1) {
        const float* r0 = u + bx * NX;
        const float* r1 = r0 + NX;
        float4* qrow = g_quad + (bx << 10);
        for (int iy = threadIdx.x; iy < NX - 1; iy += BLOCK_T) {
            float4 q;
            q.x = r0[iy];
            q.y = r1[iy];
            q.z = r0[iy + 1];
            q.w = r1[iy + 1];
            qrow[iy] = q;
        }
    } else if (bx == NX - 1) {
        build_one_grid(incx, g_cellx);
    } else {
        build_one_grid(incy, g_celly);
    }
}

// ---------------------------------------------------------------------------
// Eval: branch-free single-step locate (grid deviates < 0.5 index units from
// uniform, so the true cell is within +-1 of floor(1023x); one signed step
// always suffices — verified bit-identical rel_err in R4/R5). No BSSY/BSYNC.
// ---------------------------------------------------------------------------
__device__ __forceinline__ int locate(float x, const float2* __restrict__ sc,
                                      float& t) {
    int i = min(max(__float2int_rd(x * 1023.0f), 0), NCELL - 1);
    float2 c = sc[i];
    float t0 = (x - c.x) * c.y;
    int step = (int)(t0 >= 1.0f) - (int)(t0 < 0.0f);
    i = min(max(i + step, 0), NCELL - 1);
    c = sc[i];
    t = (x - c.x) * c.y;
    return i;
}

__device__ __forceinline__ float blend(float tx, float ty, float4 q) {
    float a = fmaf(tx, q.y - q.x, q.x);
    float b = fmaf(tx, q.w - q.z, q.z);
    return fmaf(ty, b - a, a);
}

__global__ __launch_bounds__(BLOCK_T)
void eval_kernel(const float4* __restrict__ xe4, float4* __restrict__ out4,
                 const float2* __restrict__ xe2, float* __restrict__ outs,
                 int n) {
    __shared__ float2 scx[NCELL];
    __shared__ float2 scy[NCELL];
    for (int i = threadIdx.x; i < NCELL; i += BLOCK_T) {
        scx[i] = g_cellx[i];
        scy[i] = g_celly[i];
    }
    __syncthreads();

    int gid = blockIdx.x * BLOCK_T + threadIdx.x;
    int p0  = gid * PTS_PER_THREAD;

    if (p0 + PTS_PER_THREAD <= n) {
        // one group of 4 points: 2 coalesced float4 loads
        float4 a = __ldcs(&xe4[gid * 2 + 0]);
        float4 b = __ldcs(&xe4[gid * 2 + 1]);
        float px[4] = {a.x, a.z, b.x, b.z};
        float py[4] = {a.y, a.w, b.y, b.w};

        int ix[4], iy[4];
        float tx[4], ty[4];
        #pragma unroll
        for (int k = 0; k < 4; k++) {
            ix[k] = locate(px[k], scx, tx[k]);
            iy[k] = locate(py[k], scy, ty[k]);
        }
        float4 q[4];
        #pragma unroll
        for (int k = 0; k < 4; k++)
            q[k] = __ldg(&g_quad[(ix[k] << 10) + iy[k]]);

        float4 r;
        r.x = blend(tx[0], ty[0], q[0]);
        r.y = blend(tx[1], ty[1], q[1]);
        r.z = blend(tx[2], ty[2], q[2]);
        r.w = blend(tx[3], ty[3], q[3]);
        __stcs(&out4[gid], r);
    } else {
        for (int i = p0; i < n; i++) {
            float2 p = xe2[i];
            float tx, ty;
            int ix = locate(p.x, scx, tx);
            int iy = locate(p.y, scy, ty);
            float4 q = __ldg(&g_quad[(ix << 10) + iy]);
            outs[i] = blend(tx, ty, q);
        }
    }
}

// ---------------------------------------------------------------------------
extern "C" void kernel_launch(void* const* d_in, const int* in_sizes, int n_in,
                              void* d_out, int out_size) {
    const float* xe   = (const float*)d_in[0];
    const float* incx = (const float*)d_in[1];
    const float* incy = (const float*)d_in[2];
    const float* u    = (const float*)d_in[3];
    int n = out_size;   // 8,000,000

    build_all<<<(NX - 1) + 2, BLOCK_T>>>(incx, incy, u);

    int threads_needed = (n + PTS_PER_THREAD - 1) / PTS_PER_THREAD;
    int blocks = (threads_needed + BLOCK_T - 1) / BLOCK_T;
    eval_kernel<<<blocks, BLOCK_T>>>((const float4*)xe, (float4*)d_out,
                                     (const float2*)xe, (float*)d_out, n);
}

// round 10
// speedup vs baseline: 1.3333x; 1.3333x over previous
#include <cuda_runtime.h>
#include <cuda_bf16.h>

#define NX 1024
#define NCELL 1023
#define EPSV 1e-10f
#define BLOCK_T 256
#define EVAL_BLOCKS 1184   // 8 blocks/SM x 148 SMs: one persistent wave

// Scratch (__device__ globals — allocation-free rule)
__device__ float2 g_cellx[NCELL];           // (x_i, 1/max(dx,EPS)) per cell
__device__ float2 g_celly[NCELL];
__device__ float4 g_quad[(NX - 1) * NX];    // {u00,u10,u01,u11} per cell (ix<<10 | iy)

// ---------------------------------------------------------------------------
// Builder: blocks 0..1022 pack quad rows; blocks 1023/1024 build the x/y
// adaptive grids (shfl scan) and emit the per-cell (x_i, rdx) tables.
// ---------------------------------------------------------------------------
__device__ __forceinline__ void build_one_grid(const float* __restrict__ inc,
                                               float2* __restrict__ cells) {
    __shared__ float scum[1024];
    __shared__ float sg[1024];
    __shared__ float swarp[8];

    const int t    = threadIdx.x;       // 0..255
    const int lane = t & 31;
    const int warp = t >> 5;

    float v[4];
    #pragma unroll
    for (int j = 0; j < 4; j++) {
        int idx = 4 * t + j;
        float val = 0.0f;
        if (idx < 1023) {
            float xv = inc[idx];
            float sp = fmaxf(xv, 0.0f) + log1pf(expf(-fabsf(xv)));  // softplus
            val = fmaxf(sp, 1e-6f);
        }
        v[j] = val;
    }
    float c0 = v[0];
    float c1 = c0 + v[1];
    float c2 = c1 + v[2];
    float c3 = c2 + v[3];

    float incl = c3;
    #pragma unroll
    for (int off = 1; off < 32; off <<= 1) {
        float up = __shfl_up_sync(0xffffffff, incl, off);
        if (lane >= off) incl += up;
    }
    float thr_excl = incl - c3;
    if (lane == 31) swarp[warp] = incl;
    __syncthreads();

    if (warp == 0 && lane < 8) {
        float w = swarp[lane];
        #pragma unroll
        for (int off = 1; off < 8; off <<= 1) {
            float up = __shfl_up_sync(0xff, w, off);
            if (lane >= off) w += up;
        }
        swarp[lane] = w - swarp[lane];
    }
    __syncthreads();

    float pref = swarp[warp] + thr_excl;
    scum[4 * t + 0] = pref + c0;
    scum[4 * t + 1] = pref + c1;
    scum[4 * t + 2] = pref + c2;
    scum[4 * t + 3] = pref + c3;
    __syncthreads();

    float total = scum[1022];
    if (t == 0) sg[0] = 0.0f;
    #pragma unroll
    for (int j = 0; j < 4; j++) {
        int idx = 4 * t + j;
        if (idx < 1022)       sg[idx + 1] = scum[idx] / total;
        else if (idx == 1022) sg[1023]    = 1.0f;
    }
    __syncthreads();

    #pragma unroll
    for (int j = 0; j < 4; j++) {
        int idx = 4 * t + j;
        if (idx < NCELL) {
            float xi  = sg[idx];
            float rdx = 1.0f / fmaxf(sg[idx + 1] - xi, EPSV);
            cells[idx] = make_float2(xi, rdx);
        }
    }
}

__global__ __launch_bounds__(BLOCK_T)
void build_all(const float* __restrict__ incx,
               const float* __restrict__ incy,
               const float* __restrict__ u) {
    int bx = blockIdx.x;
    if (bx < NX - 1) {
        const float* r0 = u + bx * NX;
        const float* r1 = r0 + NX;
        float4* qrow = g_quad + (bx << 10);
        for (int iy = threadIdx.x; iy < NX - 1; iy += BLOCK_T) {
            float4 q;
            q.x = r0[iy];
            q.y = r1[iy];
            q.z = r0[iy + 1];
            q.w = r1[iy + 1];
            qrow[iy] = q;
        }
    } else if (bx == NX - 1) {
        build_one_grid(incx, g_cellx);
    } else {
        build_one_grid(incy, g_celly);
    }
}

// ---------------------------------------------------------------------------
// Eval (persistent): R7 body, grid-stride over 4-point groups. Lazy-probe
// locate (cheapest average smem bytes: ~8.2B/pt/dim; R9 proved forced 16B
// costs +6us of smem port time).
// ---------------------------------------------------------------------------
__device__ __forceinline__ int locate(float x, const float2* __restrict__ sc,
                                      float& t) {
    int i = min(max(__float2int_rd(x * 1023.0f), 0), NCELL - 1);
    float2 c = sc[i];
    t = (x - c.x) * c.y;
    while (t < 0.0f && i > 0)            { c = sc[--i]; t = (x - c.x) * c.y; }
    while (t >= 1.0f && i < NCELL - 1)   { c = sc[++i]; t = (x - c.x) * c.y; }
    return i;
}

__device__ __forceinline__ float blend(float tx, float ty, float4 q) {
    float a = fmaf(tx, q.y - q.x, q.x);
    float b = fmaf(tx, q.w - q.z, q.z);
    return fmaf(ty, b - a, a);
}

__global__ __launch_bounds__(BLOCK_T)
void eval_kernel(const float4* __restrict__ xe4, float4* __restrict__ out4,
                 const float2* __restrict__ xe2, float* __restrict__ outs,
                 int n) {
    __shared__ float2 scx[NCELL];
    __shared__ float2 scy[NCELL];
    for (int i = threadIdx.x; i < NCELL; i += BLOCK_T) {
        scx[i] = g_cellx[i];
        scy[i] = g_celly[i];
    }
    __syncthreads();

    const int ngroups = n >> 2;                  // full 4-point groups
    const int stride  = gridDim.x * BLOCK_T;

    #pragma unroll 1
    for (int g = blockIdx.x * BLOCK_T + threadIdx.x; g < ngroups; g += stride) {
        // one group of 4 points: 2 coalesced float4 loads
        float4 a = __ldcs(&xe4[g * 2 + 0]);
        float4 b = __ldcs(&xe4[g * 2 + 1]);
        float px[4] = {a.x, a.z, b.x, b.z};
        float py[4] = {a.y, a.w, b.y, b.w};

        int ix[4], iy[4];
        float tx[4], ty[4];
        #pragma unroll
        for (int k = 0; k < 4; k++) {
            ix[k] = locate(px[k], scx, tx[k]);
            iy[k] = locate(py[k], scy, ty[k]);
        }
        float4 q[4];
        #pragma unroll
        for (int k = 0; k < 4; k++)
            q[k] = __ldg(&g_quad[(ix[k] << 10) + iy[k]]);

        float4 r;
        r.x = blend(tx[0], ty[0], q[0]);
        r.y = blend(tx[1], ty[1], q[1]);
        r.z = blend(tx[2], ty[2], q[2]);
        r.w = blend(tx[3], ty[3], q[3]);
        __stcs(&out4[g], r);
    }

    // scalar tail (never runs when n % 4 == 0, e.g. n = 8,000,000)
    int tail = ngroups << 2;
    if (blockIdx.x == 0) {
        for (int i = tail + threadIdx.x; i < n; i += BLOCK_T) {
            float2 p = xe2[i];
            float tx, ty;
            int ixx = locate(p.x, scx, tx);
            int iyy = locate(p.y, scy, ty);
            float4 q = __ldg(&g_quad[(ixx << 10) + iyy]);
            outs[i] = blend(tx, ty, q);
        }
    }
}

// ---------------------------------------------------------------------------
extern "C" void kernel_launch(void* const* d_in, const int* in_sizes, int n_in,
                              void* d_out, int out_size) {
    const float* xe   = (const float*)d_in[0];
    const float* incx = (const float*)d_in[1];
    const float* incy = (const float*)d_in[2];
    const float* u    = (const float*)d_in[3];
    int n = out_size;   // 8,000,000

    build_all<<<(NX - 1) + 2, BLOCK_T>>>(incx, incy, u);

    eval_kernel<<<EVAL_BLOCKS, BLOCK_T>>>((const float4*)xe, (float4*)d_out,
                                          (const float2*)xe, (float*)d_out, n);
}

// round 11
// speedup vs baseline: 1.3543x; 1.0157x over previous
#include <cuda_runtime.h>
#include <cuda_bf16.h>

#define NX 1024
#define NCELL 1023
#define EPSV 1e-10f
#define BLOCK_T 256
#define EVAL_BLOCKS 1184   // 8 blocks/SM x 148 SMs: one persistent wave

// Scratch (__device__ globals — allocation-free rule)
__device__ float2 g_cellx[NCELL];           // (x_i, 1/max(dx,EPS)) per cell
__device__ float2 g_celly[NCELL];
__device__ float4 g_quad[(NX - 1) * NX];    // {u00,u10,u01,u11} per cell (ix<<10 | iy)

// ---------------------------------------------------------------------------
// Builder: blocks 0..1022 pack quad rows; blocks 1023/1024 build the x/y
// adaptive grids (shfl scan) and emit the per-cell (x_i, rdx) tables.
// ---------------------------------------------------------------------------
__device__ __forceinline__ void build_one_grid(const float* __restrict__ inc,
                                               float2* __restrict__ cells) {
    __shared__ float scum[1024];
    __shared__ float sg[1024];
    __shared__ float swarp[8];

    const int t    = threadIdx.x;       // 0..255
    const int lane = t & 31;
    const int warp = t >> 5;

    float v[4];
    #pragma unroll
    for (int j = 0; j < 4; j++) {
        int idx = 4 * t + j;
        float val = 0.0f;
        if (idx < 1023) {
            float xv = inc[idx];
            float sp = fmaxf(xv, 0.0f) + log1pf(expf(-fabsf(xv)));  // softplus
            val = fmaxf(sp, 1e-6f);
        }
        v[j] = val;
    }
    float c0 = v[0];
    float c1 = c0 + v[1];
    float c2 = c1 + v[2];
    float c3 = c2 + v[3];

    float incl = c3;
    #pragma unroll
    for (int off = 1; off < 32; off <<= 1) {
        float up = __shfl_up_sync(0xffffffff, incl, off);
        if (lane >= off) incl += up;
    }
    float thr_excl = incl - c3;
    if (lane == 31) swarp[warp] = incl;
    __syncthreads();

    if (warp == 0 && lane < 8) {
        float w = swarp[lane];
        #pragma unroll
        for (int off = 1; off < 8; off <<= 1) {
            float up = __shfl_up_sync(0xff, w, off);
            if (lane >= off) w += up;
        }
        swarp[lane] = w - swarp[lane];
    }
    __syncthreads();

    float pref = swarp[warp] + thr_excl;
    scum[4 * t + 0] = pref + c0;
    scum[4 * t + 1] = pref + c1;
    scum[4 * t + 2] = pref + c2;
    scum[4 * t + 3] = pref + c3;
    __syncthreads();

    float total = scum[1022];
    if (t == 0) sg[0] = 0.0f;
    #pragma unroll
    for (int j = 0; j < 4; j++) {
        int idx = 4 * t + j;
        if (idx < 1022)       sg[idx + 1] = scum[idx] / total;
        else if (idx == 1022) sg[1023]    = 1.0f;
    }
    __syncthreads();

    #pragma unroll
    for (int j = 0; j < 4; j++) {
        int idx = 4 * t + j;
        if (idx < NCELL) {
            float xi  = sg[idx];
            float rdx = 1.0f / fmaxf(sg[idx + 1] - xi, EPSV);
            cells[idx] = make_float2(xi, rdx);
        }
    }
}

__global__ __launch_bounds__(BLOCK_T)
void build_all(const float* __restrict__ incx,
               const float* __restrict__ incy,
               const float* __restrict__ u) {
    int bx = blockIdx.x;
    if (bx < NX - 1) {
        const float* r0 = u + bx * NX;
        const float* r1 = r0 + NX;
        float4* qrow = g_quad + (bx << 10);
        for (int iy = threadIdx.x; iy < NX - 1; iy += BLOCK_T) {
            float4 q;
            q.x = r0[iy];
            q.y = r1[iy];
            q.z = r0[iy + 1];
            q.w = r1[iy + 1];
            qrow[iy] = q;
        }
    } else if (bx == NX - 1) {
        build_one_grid(incx, g_cellx);
    } else {
        build_one_grid(incy, g_celly);
    }
}

// ---------------------------------------------------------------------------
// Eval (persistent + prefetch): 2 points per thread per iteration (one
// float4 of xe), with the NEXT iteration's xe float4 prefetched via a
// clamped index (branch-free, always-valid). Lazy-probe locate (R9 proved
// forced extra LDS costs smem-port time).
// ---------------------------------------------------------------------------
__device__ __forceinline__ int locate(float x, const float2* __restrict__ sc,
                                      float& t) {
    int i = min(max(__float2int_rd(x * 1023.0f), 0), NCELL - 1);
    float2 c = sc[i];
    t = (x - c.x) * c.y;
    while (t < 0.0f && i > 0)            { c = sc[--i]; t = (x - c.x) * c.y; }
    while (t >= 1.0f && i < NCELL - 1)   { c = sc[++i]; t = (x - c.x) * c.y; }
    return i;
}

__device__ __forceinline__ float blend(float tx, float ty, float4 q) {
    float a = fmaf(tx, q.y - q.x, q.x);
    float b = fmaf(tx, q.w - q.z, q.z);
    return fmaf(ty, b - a, a);
}

__global__ __launch_bounds__(BLOCK_T)
void eval_kernel(const float4* __restrict__ xe4, float2* __restrict__ out2,
                 const float2* __restrict__ xe2, float* __restrict__ outs,
                 int n) {
    __shared__ float2 scx[NCELL];
    __shared__ float2 scy[NCELL];
    for (int i = threadIdx.x; i < NCELL; i += BLOCK_T) {
        scx[i] = g_cellx[i];
        scy[i] = g_celly[i];
    }
    __syncthreads();

    const int ngroups = n >> 1;                  // 2-point groups
    const int stride  = gridDim.x * BLOCK_T;
    const int glast   = ngroups - 1;

    int g0 = blockIdx.x * BLOCK_T + threadIdx.x;
    float4 a = __ldcs(&xe4[min(g0, glast)]);     // always-valid primer

    #pragma unroll 1
    for (int g = g0; g < ngroups; g += stride) {
        // prefetch next iteration's xe (clamped -> branch-free, never faults)
        float4 an = __ldcs(&xe4[min(g + stride, glast)]);

        float px0 = a.x, py0 = a.y;
        float px1 = a.z, py1 = a.w;

        float tx0, ty0, tx1, ty1;
        int ix0 = locate(px0, scx, tx0);
        int iy0 = locate(py0, scy, ty0);
        int ix1 = locate(px1, scx, tx1);
        int iy1 = locate(py1, scy, ty1);

        float4 q0 = __ldg(&g_quad[(ix0 << 10) + iy0]);
        float4 q1 = __ldg(&g_quad[(ix1 << 10) + iy1]);

        float2 r;
        r.x = blend(tx0, ty0, q0);
        r.y = blend(tx1, ty1, q1);
        __stcs(&out2[g], r);

        a = an;
    }

    // scalar tail (never runs when n % 2 == 0, e.g. n = 8,000,000)
    int tail = ngroups << 1;
    if (blockIdx.x == 0) {
        for (int i = tail + threadIdx.x; i < n; i += BLOCK_T) {
            float2 p = xe2[i];
            float tx, ty;
            int ixx = locate(p.x, scx, tx);
            int iyy = locate(p.y, scy, ty);
            float4 q = __ldg(&g_quad[(ixx << 10) + iyy]);
            outs[i] = blend(tx, ty, q);
        }
    }
}

// ---------------------------------------------------------------------------
extern "C" void kernel_launch(void* const* d_in, const int* in_sizes, int n_in,
                              void* d_out, int out_size) {
    const float* xe   = (const float*)d_in[0];
    const float* incx = (const float*)d_in[1];
    const float* incy = (const float*)d_in[2];
    const float* u    = (const float*)d_in[3];
    int n = out_size;   // 8,000,000

    build_all<<<(NX - 1) + 2, BLOCK_T>>>(incx, incy, u);

    eval_kernel<<<EVAL_BLOCKS, BLOCK_T>>>((const float4*)xe, (float2*)d_out,
                                          (const float2*)xe, (float*)d_out, n);
}